// round 1
// baseline (speedup 1.0000x reference)
#include <cuda_runtime.h>

#define BB 2
#define SS 2048
#define DD 256
#define HH 8
#define DH 32
#define NROWS (BB*SS)   // 4096

// Scratch (device globals: no allocation allowed)
__device__ float g_q[NROWS*DD];
__device__ float g_k[NROWS*DD];
__device__ float g_v[NROWS*DD];
__device__ float g_ctx[NROWS*DD];
__device__ float g_tmp[NROWS*DD];
__device__ float g_sqq[NROWS*HH];
__device__ float g_sqk[NROWS*HH];

// ---------------------------------------------------------------------------
// GEMM: C[m,n] = sum_k A[m,k] * W[n,k] + bias[n]   (A: [M,256], W: [256,256])
// 64x64 block tile, 256 threads, 4x4 per thread, K-step 16.
// ---------------------------------------------------------------------------
__global__ __launch_bounds__(256) void gemm_bias(
    const float* __restrict__ A, const float* __restrict__ W,
    const float* __restrict__ bias, float* __restrict__ C)
{
    __shared__ __align__(16) float As[16][68];
    __shared__ __align__(16) float Bs[16][68];

    const int tid = threadIdx.x;
    const int m0 = blockIdx.y * 64;
    const int n0 = blockIdx.x * 64;
    const int lr = tid >> 2;   // 0..63 (row within tile)
    const int lv = tid & 3;    // which float4 along K
    const int tx = tid & 15;
    const int ty = tid >> 4;

    float c00=0,c01=0,c02=0,c03=0, c10=0,c11=0,c12=0,c13=0;
    float c20=0,c21=0,c22=0,c23=0, c30=0,c31=0,c32=0,c33=0;

    for (int k0 = 0; k0 < DD; k0 += 16) {
        float4 av = *(const float4*)&A[(m0 + lr) * DD + k0 + lv * 4];
        float4 bv = *(const float4*)&W[(n0 + lr) * DD + k0 + lv * 4];
        __syncthreads();
        As[lv*4+0][lr] = av.x; As[lv*4+1][lr] = av.y;
        As[lv*4+2][lr] = av.z; As[lv*4+3][lr] = av.w;
        Bs[lv*4+0][lr] = bv.x; Bs[lv*4+1][lr] = bv.y;
        Bs[lv*4+2][lr] = bv.z; Bs[lv*4+3][lr] = bv.w;
        __syncthreads();
        #pragma unroll
        for (int kk = 0; kk < 16; kk++) {
            float4 a4 = *(const float4*)&As[kk][ty * 4];
            float4 b4 = *(const float4*)&Bs[kk][tx * 4];
            c00 = fmaf(a4.x, b4.x, c00); c01 = fmaf(a4.x, b4.y, c01);
            c02 = fmaf(a4.x, b4.z, c02); c03 = fmaf(a4.x, b4.w, c03);
            c10 = fmaf(a4.y, b4.x, c10); c11 = fmaf(a4.y, b4.y, c11);
            c12 = fmaf(a4.y, b4.z, c12); c13 = fmaf(a4.y, b4.w, c13);
            c20 = fmaf(a4.z, b4.x, c20); c21 = fmaf(a4.z, b4.y, c21);
            c22 = fmaf(a4.z, b4.z, c22); c23 = fmaf(a4.z, b4.w, c23);
            c30 = fmaf(a4.w, b4.x, c30); c31 = fmaf(a4.w, b4.y, c31);
            c32 = fmaf(a4.w, b4.z, c32); c33 = fmaf(a4.w, b4.w, c33);
        }
    }

    const int n = n0 + tx * 4;
    float4 bb = *(const float4*)&bias[n];
    float4 o;
    o.x = c00 + bb.x; o.y = c01 + bb.y; o.z = c02 + bb.z; o.w = c03 + bb.w;
    *(float4*)&C[(m0 + ty*4 + 0) * DD + n] = o;
    o.x = c10 + bb.x; o.y = c11 + bb.y; o.z = c12 + bb.z; o.w = c13 + bb.w;
    *(float4*)&C[(m0 + ty*4 + 1) * DD + n] = o;
    o.x = c20 + bb.x; o.y = c21 + bb.y; o.z = c22 + bb.z; o.w = c23 + bb.w;
    *(float4*)&C[(m0 + ty*4 + 2) * DD + n] = o;
    o.x = c30 + bb.x; o.y = c31 + bb.y; o.z = c32 + bb.z; o.w = c33 + bb.w;
    *(float4*)&C[(m0 + ty*4 + 3) * DD + n] = o;
}

// ---------------------------------------------------------------------------
// expmap0 per (row, head): one warp handles one 32-dim head vector.
// Also writes sq = tanh(norm)^2 = squared norm of the mapped vector.
// ---------------------------------------------------------------------------
__global__ __launch_bounds__(256) void expmap_kernel(
    float* __restrict__ p, float* __restrict__ sq)
{
    const int row  = blockIdx.x;           // 0..NROWS-1
    const int h    = threadIdx.x >> 5;     // 0..7
    const int lane = threadIdx.x & 31;
    const int idx  = row * DD + h * DH + lane;
    float v = p[idx];
    float s = v * v;
    #pragma unroll
    for (int o = 16; o; o >>= 1) s += __shfl_xor_sync(0xffffffffu, s, o);
    float n2   = fmaxf(s, 1e-12f);
    float nrm  = sqrtf(n2);
    float t    = tanhf(nrm);
    p[idx] = v * (t / nrm);
    if (lane == 0) sq[row * HH + h] = t * t;
}

// ---------------------------------------------------------------------------
// Hyperbolic-distance attention.
// One thread per query row; block = 128 queries of one (b,h); keys tiled
// through shared memory in chunks of 128. Scores are always in [-2.2, 0]
// (dist >= 0, atanh clipped), so plain sum-of-exp softmax is safe: no
// running-max bookkeeping needed.
// ---------------------------------------------------------------------------
#define QT 128
#define KT 128

__global__ __launch_bounds__(128) void attn_kernel(
    const float* __restrict__ q, const float* __restrict__ k,
    const float* __restrict__ v, const float* __restrict__ sqq,
    const float* __restrict__ sqk, float* __restrict__ ctx)
{
    __shared__ __align__(16) float sk[KT][DH];
    __shared__ __align__(16) float sv[KT][DH];
    __shared__ float skk[KT];

    const int b  = blockIdx.z;
    const int h  = blockIdx.y;
    const int s0 = blockIdx.x * QT;
    const int tid  = threadIdx.x;
    const int srow = s0 + tid;

    const float* qp = q + ((b * SS + srow) * DD + h * DH);
    float qr[DH];
    #pragma unroll
    for (int j = 0; j < 8; j++) ((float4*)qr)[j] = ((const float4*)qp)[j];
    const float qq = sqq[(b * SS + srow) * HH + h];
    const float Bq = 1.0f - qq;

    float acc[DH];
    #pragma unroll
    for (int d = 0; d < DH; d++) acc[d] = 0.0f;
    float l = 0.0f;

    for (int t0 = 0; t0 < SS; t0 += KT) {
        __syncthreads();
        for (int idx = tid; idx < KT * 8; idx += 128) {
            int t = idx >> 3, j = idx & 7;
            const float* kp = k + ((b * SS + t0 + t) * DD + h * DH);
            const float* vp = v + ((b * SS + t0 + t) * DD + h * DH);
            ((float4*)sk[t])[j] = ((const float4*)kp)[j];
            ((float4*)sv[t])[j] = ((const float4*)vp)[j];
        }
        skk[tid] = sqk[(b * SS + t0 + tid) * HH + h];
        __syncthreads();

        for (int t = 0; t < KT; t++) {
            const float4* kp4 = (const float4*)sk[t];
            float p0 = 0.f, p1 = 0.f, p2 = 0.f, p3 = 0.f;
            #pragma unroll
            for (int j = 0; j < 8; j++) {
                float4 kv = kp4[j];
                p0 = fmaf(qr[4*j+0], kv.x, p0);
                p1 = fmaf(qr[4*j+1], kv.y, p1);
                p2 = fmaf(qr[4*j+2], kv.z, p2);
                p3 = fmaf(qr[4*j+3], kv.w, p3);
            }
            float qk = (p0 + p1) + (p2 + p3);
            float kk = skk[t];

            float Aq   = 1.0f - 2.0f * qk + kk;
            float den  = 1.0f - 2.0f * qk + qq * kk;
            float num2 = Aq * Aq * qq + Bq * Bq * kk - 2.0f * Aq * Bq * qk;
            num2 = fmaxf(num2, 0.0f);
            float nn = num2 * rsqrtf(fmaxf(num2, 1e-38f));   // sqrt(num2)
            float da = fmaxf(fabsf(den), 1e-12f);
            float n  = fminf(__fdividef(nn, da), 0.99999f);
            float r  = __fdividef(1.0f + n, 1.0f - n);       // exp(dist)
            // w = exp(-dist/sqrt(dh)) = r^(-1/sqrt(32))
            float w  = __expf(-0.17677669529663689f * __logf(r));
            l += w;

            const float4* vp4 = (const float4*)sv[t];
            #pragma unroll
            for (int j = 0; j < 8; j++) {
                float4 vv = vp4[j];
                acc[4*j+0] = fmaf(w, vv.x, acc[4*j+0]);
                acc[4*j+1] = fmaf(w, vv.y, acc[4*j+1]);
                acc[4*j+2] = fmaf(w, vv.z, acc[4*j+2]);
                acc[4*j+3] = fmaf(w, vv.w, acc[4*j+3]);
            }
        }
    }

    const float linv = __fdividef(1.0f, l);
    float* op = ctx + ((b * SS + srow) * DD + h * DH);
    #pragma unroll
    for (int j = 0; j < 8; j++) {
        float4 o;
        o.x = acc[4*j+0] * linv; o.y = acc[4*j+1] * linv;
        o.z = acc[4*j+2] * linv; o.w = acc[4*j+3] * linv;
        ((float4*)op)[j] = o;
    }
}

// ---------------------------------------------------------------------------

extern "C" void kernel_launch(void* const* d_in, const int* in_sizes, int n_in,
                              void* d_out, int out_size)
{
    const float* x   = (const float*)d_in[0];
    const float* Wq  = (const float*)d_in[1];
    const float* bq  = (const float*)d_in[2];
    const float* Wk  = (const float*)d_in[3];
    const float* bk  = (const float*)d_in[4];
    const float* Wv  = (const float*)d_in[5];
    const float* bv  = (const float*)d_in[6];
    const float* Wo  = (const float*)d_in[7];
    const float* bo  = (const float*)d_in[8];
    const float* Wfc = (const float*)d_in[9];
    const float* bfc = (const float*)d_in[10];
    float* out = (float*)d_out;

    float *q, *k, *v, *ctx, *tmp, *sqq, *sqk;
    cudaGetSymbolAddress((void**)&q,   g_q);
    cudaGetSymbolAddress((void**)&k,   g_k);
    cudaGetSymbolAddress((void**)&v,   g_v);
    cudaGetSymbolAddress((void**)&ctx, g_ctx);
    cudaGetSymbolAddress((void**)&tmp, g_tmp);
    cudaGetSymbolAddress((void**)&sqq, g_sqq);
    cudaGetSymbolAddress((void**)&sqk, g_sqk);

    dim3 ggrid(DD / 64, NROWS / 64);
    gemm_bias<<<ggrid, 256>>>(x, Wq, bq, q);
    gemm_bias<<<ggrid, 256>>>(x, Wk, bk, k);
    gemm_bias<<<ggrid, 256>>>(x, Wv, bv, v);

    expmap_kernel<<<NROWS, 256>>>(q, sqq);
    expmap_kernel<<<NROWS, 256>>>(k, sqk);

    dim3 agrid(SS / QT, HH, BB);
    attn_kernel<<<agrid, 128>>>(q, k, v, sqq, sqk, ctx);

    gemm_bias<<<ggrid, 256>>>(ctx, Wo, bo, tmp);
    gemm_bias<<<ggrid, 256>>>(tmp, Wfc, bfc, out);
}

// round 3
// speedup vs baseline: 1.2861x; 1.2861x over previous
#include <cuda_runtime.h>

#define BB 2
#define SS 2048
#define DD 256
#define HH 8
#define DH 32
#define NROWS (BB*SS)   // 4096

// Scratch (device globals: no allocation allowed)
__device__ float g_q[NROWS*DD];
__device__ float g_k[NROWS*DD];
__device__ float g_v[NROWS*DD];
__device__ float g_ctx[NROWS*DD];
__device__ float g_sqq[NROWS*HH];
__device__ float g_sqk[NROWS*HH];
__device__ float g_wc[DD*DD];
__device__ float g_bc[DD];

typedef unsigned long long u64;

// ---- Blackwell packed f32x2 helpers (FFMA2: 2 fp32 FMAs per instruction) ----
__device__ __forceinline__ u64 ffma2(u64 a, u64 b, u64 c){
    u64 d; asm("fma.rn.f32x2 %0, %1, %2, %3;" : "=l"(d) : "l"(a), "l"(b), "l"(c)); return d;
}
__device__ __forceinline__ u64 fadd2(u64 a, u64 b){
    u64 d; asm("add.rn.f32x2 %0, %1, %2;" : "=l"(d) : "l"(a), "l"(b)); return d;
}
__device__ __forceinline__ u64 pack2(float x, float y){
    u64 r; asm("mov.b64 %0, {%1, %2};" : "=l"(r) : "f"(x), "f"(y)); return r;
}
__device__ __forceinline__ float2 unpack2(u64 a){
    float2 f; asm("mov.b64 {%0, %1}, %2;" : "=f"(f.x), "=f"(f.y) : "l"(a)); return f;
}

// ---------------------------------------------------------------------------
// GEMM body: C[m,n] = sum_k A[m,k] * W[n,k] + bias[n]
// 64x64 tile, 256 threads, 4 rows x 4 cols per thread, K-step 16, FFMA2 inner.
// ---------------------------------------------------------------------------
__device__ __forceinline__ void gemm_body(
    const float* __restrict__ A, const float* __restrict__ W,
    const float* __restrict__ bias, float* __restrict__ C,
    int m0, int n0)
{
    __shared__ __align__(16) float As[16][68];
    __shared__ __align__(16) float Bs[16][68];

    const int tid = threadIdx.x;
    const int lr = tid >> 2;
    const int lv = tid & 3;
    const int tx = tid & 15;
    const int ty = tid >> 4;

    u64 c2[4][2];
    #pragma unroll
    for (int r = 0; r < 4; r++) { c2[r][0] = 0ull; c2[r][1] = 0ull; }

    for (int k0 = 0; k0 < DD; k0 += 16) {
        float4 av = *(const float4*)&A[(m0 + lr) * DD + k0 + lv * 4];
        float4 bv = *(const float4*)&W[(n0 + lr) * DD + k0 + lv * 4];
        __syncthreads();
        As[lv*4+0][lr] = av.x; As[lv*4+1][lr] = av.y;
        As[lv*4+2][lr] = av.z; As[lv*4+3][lr] = av.w;
        Bs[lv*4+0][lr] = bv.x; Bs[lv*4+1][lr] = bv.y;
        Bs[lv*4+2][lr] = bv.z; Bs[lv*4+3][lr] = bv.w;
        __syncthreads();
        #pragma unroll
        for (int kk = 0; kk < 16; kk++) {
            float4 a4 = *(const float4*)&As[kk][ty * 4];
            ulonglong2 bp = *(const ulonglong2*)&Bs[kk][tx * 4];
            u64 a0 = pack2(a4.x, a4.x);
            u64 a1 = pack2(a4.y, a4.y);
            u64 a2 = pack2(a4.z, a4.z);
            u64 a3 = pack2(a4.w, a4.w);
            c2[0][0] = ffma2(a0, bp.x, c2[0][0]); c2[0][1] = ffma2(a0, bp.y, c2[0][1]);
            c2[1][0] = ffma2(a1, bp.x, c2[1][0]); c2[1][1] = ffma2(a1, bp.y, c2[1][1]);
            c2[2][0] = ffma2(a2, bp.x, c2[2][0]); c2[2][1] = ffma2(a2, bp.y, c2[2][1]);
            c2[3][0] = ffma2(a3, bp.x, c2[3][0]); c2[3][1] = ffma2(a3, bp.y, c2[3][1]);
        }
    }

    const int n = n0 + tx * 4;
    float4 bb = *(const float4*)&bias[n];
    #pragma unroll
    for (int r = 0; r < 4; r++) {
        float2 lo = unpack2(c2[r][0]);
        float2 hi = unpack2(c2[r][1]);
        float4 o;
        o.x = lo.x + bb.x; o.y = lo.y + bb.y;
        o.z = hi.x + bb.z; o.w = hi.y + bb.w;
        *(float4*)&C[(m0 + ty*4 + r) * DD + n] = o;
    }
}

// QKV projections fused into one launch: blockIdx.z selects the matrix.
struct QKVArgs {
    const float *Wq, *bq, *Wk, *bk, *Wv, *bv;
    float *q, *k, *v;
};

__global__ __launch_bounds__(256) void gemm_qkv(const float* __restrict__ x, QKVArgs a)
{
    const float* W; const float* b; float* C;
    if (blockIdx.z == 0)      { W = a.Wq; b = a.bq; C = a.q; }
    else if (blockIdx.z == 1) { W = a.Wk; b = a.bk; C = a.k; }
    else                      { W = a.Wv; b = a.bv; C = a.v; }
    gemm_body(x, W, b, C, blockIdx.y * 64, blockIdx.x * 64);
}

__global__ __launch_bounds__(256) void gemm_single(
    const float* __restrict__ A, const float* __restrict__ W,
    const float* __restrict__ bias, float* __restrict__ C)
{
    gemm_body(A, W, bias, C, blockIdx.y * 64, blockIdx.x * 64);
}

// ---------------------------------------------------------------------------
// Wcomb = Wfc @ Wo  (so out = ctx @ Wcomb^T + bcomb, fusing two GEMMs)
// ---------------------------------------------------------------------------
__global__ __launch_bounds__(256) void wcomb_kernel(
    const float* __restrict__ Wfc, const float* __restrict__ Wo,
    float* __restrict__ Wc)
{
    __shared__ float wf[DD];
    const int n = blockIdx.x;
    const int kx = threadIdx.x;
    wf[kx] = Wfc[n * DD + kx];
    __syncthreads();
    float a0 = 0.f, a1 = 0.f, a2 = 0.f, a3 = 0.f;
    #pragma unroll 4
    for (int j = 0; j < DD; j += 4) {
        a0 = fmaf(wf[j+0], Wo[(j+0) * DD + kx], a0);
        a1 = fmaf(wf[j+1], Wo[(j+1) * DD + kx], a1);
        a2 = fmaf(wf[j+2], Wo[(j+2) * DD + kx], a2);
        a3 = fmaf(wf[j+3], Wo[(j+3) * DD + kx], a3);
    }
    Wc[n * DD + kx] = (a0 + a1) + (a2 + a3);
}

__global__ __launch_bounds__(256) void bcomb_kernel(
    const float* __restrict__ Wfc, const float* __restrict__ bo,
    const float* __restrict__ bfc, float* __restrict__ bc)
{
    const int n = threadIdx.x;
    float acc = bfc[n];
    for (int j = 0; j < DD; j++) acc = fmaf(Wfc[n * DD + j], bo[j], acc);
    bc[n] = acc;
}

// ---------------------------------------------------------------------------
// expmap0 for q and k in one launch (blockIdx.y selects tensor).
// Writes sq = tanh(norm)^2 (= squared norm of mapped vector).
// ---------------------------------------------------------------------------
__global__ __launch_bounds__(256) void expmap_kernel(
    float* __restrict__ q, float* __restrict__ k,
    float* __restrict__ sqq, float* __restrict__ sqk)
{
    float* p  = blockIdx.y ? k : q;
    float* sq = blockIdx.y ? sqk : sqq;
    const int row  = blockIdx.x;
    const int h    = threadIdx.x >> 5;
    const int lane = threadIdx.x & 31;
    const int idx  = row * DD + h * DH + lane;
    float v = p[idx];
    float s = v * v;
    #pragma unroll
    for (int o = 16; o; o >>= 1) s += __shfl_xor_sync(0xffffffffu, s, o);
    float n2  = fmaxf(s, 1e-12f);
    float nrm = sqrtf(n2);
    float t   = tanhf(nrm);
    p[idx] = v * (t / nrm);
    if (lane == 0) sq[row * HH + h] = t * t;
}

// ---------------------------------------------------------------------------
// Hyperbolic-distance attention. One thread per query row, 128-key smem tiles.
// Scores in [-2.16, 0] (dist>=0, atanh clipped) => plain sum-exp softmax.
// Weight identity: dist = 2*atanh(n) = ln((den+nn)/(den-nn)), so
//   w = exp(-dist/sqrt(32)) = __expf(ALN2 * (log2(den-nn) - log2(den+nn)))
// with ALN2 = ln2/sqrt(32). No divides; 4 MUFU ops total per pair.
// ---------------------------------------------------------------------------
#define QT 128
#define KT 128
#define ALN2 0.12253226f   /* ln2 / sqrt(32) */

__global__ __launch_bounds__(128) void attn_kernel(
    const float* __restrict__ q, const float* __restrict__ k,
    const float* __restrict__ v, const float* __restrict__ sqq,
    const float* __restrict__ sqk, float* __restrict__ ctx)
{
    __shared__ __align__(16) float sk[KT][DH];
    __shared__ __align__(16) float sv[KT][DH];
    __shared__ float skk[KT];

    const int b  = blockIdx.z;
    const int h  = blockIdx.y;
    const int s0 = blockIdx.x * QT;
    const int tid  = threadIdx.x;
    const int srow = s0 + tid;

    // q row -> packed register pairs
    const float* qp = q + ((b * SS + srow) * DD + h * DH);
    u64 qr2[16];
    #pragma unroll
    for (int j = 0; j < 8; j++) {
        float4 t4 = ((const float4*)qp)[j];
        qr2[2*j]   = pack2(t4.x, t4.y);
        qr2[2*j+1] = pack2(t4.z, t4.w);
    }
    const float qq = sqq[(b * SS + srow) * HH + h];
    const float Bq = 1.0f - qq;

    u64 acc2[16];
    #pragma unroll
    for (int d = 0; d < 16; d++) acc2[d] = 0ull;
    float l = 0.0f;

    for (int t0 = 0; t0 < SS; t0 += KT) {
        __syncthreads();
        for (int idx = tid; idx < KT * 8; idx += 128) {
            int t = idx >> 3, j = idx & 7;
            const float* kp = k + ((b * SS + t0 + t) * DD + h * DH);
            const float* vp = v + ((b * SS + t0 + t) * DD + h * DH);
            ((float4*)sk[t])[j] = ((const float4*)kp)[j];
            ((float4*)sv[t])[j] = ((const float4*)vp)[j];
        }
        skk[tid] = sqk[(b * SS + t0 + tid) * HH + h];
        __syncthreads();

        #pragma unroll 2
        for (int t = 0; t < KT; t++) {
            const ulonglong2* kp2 = (const ulonglong2*)sk[t];
            u64 s2[4] = {0ull, 0ull, 0ull, 0ull};
            #pragma unroll
            for (int j = 0; j < 8; j++) {
                ulonglong2 kv = kp2[j];
                s2[(2*j)   & 3] = ffma2(qr2[2*j],   kv.x, s2[(2*j)   & 3]);
                s2[(2*j+1) & 3] = ffma2(qr2[2*j+1], kv.y, s2[(2*j+1) & 3]);
            }
            u64 sr = fadd2(fadd2(s2[0], s2[1]), fadd2(s2[2], s2[3]));
            float2 sf = unpack2(sr);
            float qk = sf.x + sf.y;

            float kk    = skk[t];
            float t2    = 2.0f * qk;
            float Aq    = (1.0f + kk) - t2;
            float den   = fmaf(qq, kk, Aq - kk);          // 1 - 2qk + qq*kk (>= 0)
            float h1    = Bq * qk;
            float e1    = fmaf(Aq, qq, -h1);              // Aq*qq - Bq*qk
            float h2    = Aq * qk;
            float e2    = fmaf(Bq, kk, -h2);              // Bq*kk - Aq*qk
            float num2  = fmaf(Aq, e1, Bq * e2);
            num2 = fmaxf(num2, 0.0f);
            den  = fmaxf(den, 1e-12f);
            float nn = num2 * rsqrtf(fmaxf(num2, 1e-38f));   // sqrt(num2)
            float nc = fminf(nn, 0.99999f * den);            // clip n <= 1-1e-5
            float w  = __expf(ALN2 * (__log2f(den - nc) - __log2f(den + nc)));
            l += w;

            u64 w2 = pack2(w, w);
            const ulonglong2* vp2 = (const ulonglong2*)sv[t];
            #pragma unroll
            for (int j = 0; j < 8; j++) {
                ulonglong2 vv = vp2[j];
                acc2[2*j]   = ffma2(w2, vv.x, acc2[2*j]);
                acc2[2*j+1] = ffma2(w2, vv.y, acc2[2*j+1]);
            }
        }
    }

    const float linv = __fdividef(1.0f, l);
    float* op = ctx + ((b * SS + srow) * DD + h * DH);
    #pragma unroll
    for (int j = 0; j < 8; j++) {
        float2 lo = unpack2(acc2[2*j]);
        float2 hi = unpack2(acc2[2*j+1]);
        float4 o;
        o.x = lo.x * linv; o.y = lo.y * linv;
        o.z = hi.x * linv; o.w = hi.y * linv;
        ((float4*)op)[j] = o;
    }
}

// ---------------------------------------------------------------------------

extern "C" void kernel_launch(void* const* d_in, const int* in_sizes, int n_in,
                              void* d_out, int out_size)
{
    const float* x   = (const float*)d_in[0];
    const float* Wq  = (const float*)d_in[1];
    const float* bq  = (const float*)d_in[2];
    const float* Wk  = (const float*)d_in[3];
    const float* bk  = (const float*)d_in[4];
    const float* Wv  = (const float*)d_in[5];
    const float* bv  = (const float*)d_in[6];
    const float* Wo  = (const float*)d_in[7];
    const float* bo  = (const float*)d_in[8];
    const float* Wfc = (const float*)d_in[9];
    const float* bfc = (const float*)d_in[10];
    float* out = (float*)d_out;

    float *q, *k, *v, *ctx, *sqq, *sqk, *wc, *bc;
    cudaGetSymbolAddress((void**)&q,   g_q);
    cudaGetSymbolAddress((void**)&k,   g_k);
    cudaGetSymbolAddress((void**)&v,   g_v);
    cudaGetSymbolAddress((void**)&ctx, g_ctx);
    cudaGetSymbolAddress((void**)&sqq, g_sqq);
    cudaGetSymbolAddress((void**)&sqk, g_sqk);
    cudaGetSymbolAddress((void**)&wc,  g_wc);
    cudaGetSymbolAddress((void**)&bc,  g_bc);

    // Combined output weights (fuses Wo and Wfc GEMMs): runs while projections go.
    wcomb_kernel<<<DD, DD>>>(Wfc, Wo, wc);
    bcomb_kernel<<<1, DD>>>(Wfc, bo, bfc, bc);

    // Q/K/V projections in one launch
    QKVArgs a { Wq, bq, Wk, bk, Wv, bv, q, k, v };
    dim3 qkvgrid(DD / 64, NROWS / 64, 3);
    gemm_qkv<<<qkvgrid, 256>>>(x, a);

    // expmap0 on q and k (one launch)
    dim3 egrid(NROWS, 2);
    expmap_kernel<<<egrid, 256>>>(q, k, sqq, sqk);

    // attention
    dim3 agrid(SS / QT, HH, BB);
    attn_kernel<<<agrid, 128>>>(q, k, v, sqq, sqk, ctx);

    // fused output projection + fc
    dim3 ggrid(DD / 64, NROWS / 64);
    gemm_single<<<ggrid, 256>>>(ctx, wc, bc, out);
}